// round 16
// baseline (speedup 1.0000x reference)
#include <cuda_runtime.h>
#include <cuda_fp16.h>
#include <math.h>
#include <stdint.h>

#define TSAMP 64000
#define LCH 160
#define NCH 400
#define NMEL 80
#define DM 256
#define SEQ 2560
#define DFFN 1024
#define KC 64
#define KSPLIT 4

// ------------ f32 state ------------
__device__ float  g_xT[TSAMP];
__device__ float  g_sigA[NMEL * TSAMP];
__device__ float  g_sigB[NMEL * TSAMP];
__device__ float  g_b0c[4][NMEL], g_b2c[4][NMEL], g_a1c[4][NMEL], g_a2c[4][NMEL];
__device__ double g_a1d[4][NMEL], g_a2d[4][NMEL];
__device__ float  g_Mp[4][NMEL][9][4];
__device__ float  g_f1[NMEL * NCH], g_f2[NMEL * NCH];
__device__ float  g_E1[NMEL * NCH], g_E2[NMEL * NCH];
__device__ float  g_feats[NMEL * NCH];
__device__ float  g_tok[SEQ * DM];
__device__ float  g_part[KSPLIT * SEQ * DM];
__device__ float  g_ml[KSPLIT * 8 * SEQ * 2];
__device__ float  g_sc2[128], g_sh2[128], g_sc3[256], g_sh3[256];

// ------------ fp16-resident activations & weights ------------
__device__ __half g_c1h[32000 * 64];
__device__ __half g_c2h[32000 * 128];
__device__ __half g_c3h[32000 * 256];
__device__ __half g_w2rh[128 * 576];
__device__ __half g_w3rh[256 * 1152];
__device__ __half g_tokh[SEQ * DM];
__device__ __half g_qkvh[SEQ * 3 * DM];
__device__ __half g_attnOh[SEQ * DM];
__device__ __half g_ffnh[SEQ * DFFN];
__device__ __half g_wqh[8 * 768 * 256];
__device__ __half g_woh[8 * 256 * 256];
__device__ __half g_wf1h[8 * 1024 * 256];
__device__ __half g_wf2h[8 * 256 * 1024];
__device__ __half g_pwh[512 * 256];

__device__ __forceinline__ float warpSum(float v) {
#pragma unroll
    for (int o = 16; o > 0; o >>= 1) v += __shfl_xor_sync(0xffffffffu, v, o);
    return v;
}
__device__ __forceinline__ uint32_t f2h2(float x, float y) {
    __half2 h = __floats2half2_rn(x, y);
    return *(uint32_t*)&h;
}
__device__ __forceinline__ void mma16(float* d, const uint32_t* a, const uint32_t* b) {
    asm volatile(
        "mma.sync.aligned.m16n8k16.row.col.f32.f16.f16.f32 "
        "{%0,%1,%2,%3},{%4,%5,%6,%7},{%8,%9},{%0,%1,%2,%3};\n"
        : "+f"(d[0]), "+f"(d[1]), "+f"(d[2]), "+f"(d[3])
        : "r"(a[0]), "r"(a[1]), "r"(a[2]), "r"(a[3]), "r"(b[0]), "r"(b[1]));
}

// ------------------------------ cochlear ------------------------------------
__global__ void k_init() {
    int t = threadIdx.x;
    if (t < NMEL) {
        int m = t;
        double fc = exp(log(80.0) + (log(8000.0) - log(80.0)) * (double)m / 79.0);
        double omega = 2.0 * 3.141592653589793 * fc / 16000.0;
        double sn = sin(omega), cs = cos(omega);
        for (int s = 0; s < 4; s++) {
            double q = 4.0 + 2.0 * (double)s;
            double alpha = sn / (2.0 * q);
            double a0 = 1.0 + alpha;
            g_b0c[s][m] = (float)(alpha / a0);
            g_b2c[s][m] = (float)(-alpha / a0);
            g_a1c[s][m] = (float)(-2.0 * cs / a0);
            g_a2c[s][m] = (float)((1.0 - alpha) / a0);
            g_a1d[s][m] = -2.0 * cs / a0;
            g_a2d[s][m] = (1.0 - alpha) / a0;
        }
    }
    __syncthreads();
    if (t < 4 * NMEL) {
        int s = t / NMEL, m = t - s * NMEL;
        double a1 = g_a1d[s][m], a2 = g_a2d[s][m];
        double p0 = -a1, p1 = -a2, p2 = 1.0, p3 = 0.0;
        for (int it = 1; it < LCH; it++) {
            double n0 = -a1 * p0 - a2 * p2, n1 = -a1 * p1 - a2 * p3;
            p3 = p1; p2 = p0; p0 = n0; p1 = n1;
        }
        double q0 = p0, q1 = p1, q2 = p2, q3 = p3;
        for (int sp = 0; sp < 9; sp++) {
            g_Mp[s][m][sp][0] = (float)q0; g_Mp[s][m][sp][1] = (float)q1;
            g_Mp[s][m][sp][2] = (float)q2; g_Mp[s][m][sp][3] = (float)q3;
            double r0 = q0 * q0 + q1 * q2, r1 = q0 * q1 + q1 * q3;
            double r2 = q2 * q0 + q3 * q2, r3 = q2 * q1 + q3 * q3;
            q0 = r0; q1 = r1; q2 = r2; q3 = r3;
        }
    }
}

__global__ void k_transpose(const float* __restrict__ x) {
    int i = blockIdx.x * 256 + threadIdx.x;
    if (i < TSAMP) g_xT[(i % LCH) * NCH + (i / LCH)] = x[i];
}

__global__ void k_passA() {
    int idx = blockIdx.x * 256 + threadIdx.x;
    if (idx >= NMEL * NCH) return;
    int m = idx / NCH, k = idx - m * NCH;
    float b0 = g_b0c[0][m], b2 = g_b2c[0][m], a1 = g_a1c[0][m], a2 = g_a2c[0][m];
    float xm1 = 0.f, xm2 = 0.f;
    if (k > 0) { xm1 = g_xT[159 * NCH + k - 1]; xm2 = g_xT[158 * NCH + k - 1]; }
    float y1 = 0.f, y2 = 0.f;
    float* Y = g_sigA + (size_t)m * TSAMP;
    for (int t0 = 0; t0 < LCH; t0 += 8) {
        float xv[8];
#pragma unroll
        for (int u = 0; u < 8; u++) xv[u] = g_xT[(t0 + u) * NCH + k];
#pragma unroll
        for (int u = 0; u < 8; u++) {
            float y = b0 * xv[u] + b2 * xm2 - a1 * y1 - a2 * y2;
            xm2 = xm1; xm1 = xv[u]; y2 = y1; y1 = y;
            Y[(t0 + u) * NCH + k] = y;
        }
    }
    g_f1[idx] = y1;
    g_f2[idx] = y2;
}

__global__ void k_scan(int stage) {
    __shared__ float s1[2][NCH], s2[2][NCH];
    int m = blockIdx.x, t = threadIdx.x;
    if (t < NCH) { s1[0][t] = g_f1[m * NCH + t]; s2[0][t] = g_f2[m * NCH + t]; }
    __syncthreads();
    int src = 0;
#pragma unroll
    for (int sp = 0; sp < 9; sp++) {
        int off = 1 << sp;
        float M0 = g_Mp[stage][m][sp][0], M1 = g_Mp[stage][m][sp][1];
        float M2 = g_Mp[stage][m][sp][2], M3 = g_Mp[stage][m][sp][3];
        if (t < NCH) {
            float x1 = s1[src][t], x2 = s2[src][t];
            if (t >= off) {
                float p1 = s1[src][t - off], p2 = s2[src][t - off];
                x1 = fmaf(M0, p1, fmaf(M1, p2, x1));
                x2 = fmaf(M2, p1, fmaf(M3, p2, x2));
            }
            s1[src ^ 1][t] = x1; s2[src ^ 1][t] = x2;
        }
        __syncthreads();
        src ^= 1;
    }
    if (t < NCH) {
        g_E1[m * NCH + t] = t ? s1[src][t - 1] : 0.f;
        g_E2[m * NCH + t] = t ? s2[src][t - 1] : 0.f;
    }
}

template <bool LAST>
__global__ void k_passFix(int stage, int inSel) {
    int idx = blockIdx.x * 256 + threadIdx.x;
    if (idx >= NMEL * NCH) return;
    int m = idx / NCH, k = idx - m * NCH;
    const float* Y = (inSel == 0 ? g_sigA : g_sigB) + (size_t)m * TSAMP;
    float* Yn = (inSel == 0 ? g_sigB : g_sigA) + (size_t)m * TSAMP;
    float a1 = g_a1c[stage][m], a2 = g_a2c[stage][m];
    float e1 = g_E1[idx], e2 = g_E2[idx];
    float h1 = e1, h2 = e2;
    float nb0 = 0.f, nb2 = 0.f, na1 = 0.f, na2 = 0.f;
    if (!LAST) {
        nb0 = g_b0c[stage + 1][m]; nb2 = g_b2c[stage + 1][m];
        na1 = g_a1c[stage + 1][m]; na2 = g_a2c[stage + 1][m];
    }
    float nxm1 = e1, nxm2 = e2, ny1 = 0.f, ny2 = 0.f;
    float acc = 0.f;
    for (int t0 = 0; t0 < LCH; t0 += 8) {
        float yv[8];
#pragma unroll
        for (int u = 0; u < 8; u++) yv[u] = Y[(t0 + u) * NCH + k];
#pragma unroll
        for (int u = 0; u < 8; u++) {
            float h = -a1 * h1 - a2 * h2;
            h2 = h1; h1 = h;
            float y = yv[u] + h;
            if (LAST) {
                acc += fabsf(y);
            } else {
                float ny = nb0 * y + nb2 * nxm2 - na1 * ny1 - na2 * ny2;
                nxm2 = nxm1; nxm1 = y; ny2 = ny1; ny1 = ny;
                Yn[(t0 + u) * NCH + k] = ny;
            }
        }
    }
    if (LAST) {
        g_feats[idx] = logf(acc * (1.0f / 160.0f) + 1e-8f);
    } else {
        g_f1[idx] = ny1;
        g_f2[idx] = ny2;
    }
}

// ------------------------------ conv glue ------------------------------------
__global__ void k_conv1(const float* __restrict__ wt, const float* __restrict__ cb,
                        const float* __restrict__ gg, const float* __restrict__ be) {
    __shared__ float ws[576];
    __shared__ float sc[64], sh[64];
    int t = threadIdx.x;
    for (int i = t; i < 576; i += 256) ws[i] = wt[i];
    if (t < 64) {
        float s = gg[t] * rsqrtf(1.0f + 1e-5f);
        sc[t] = s;
        sh[t] = cb[t] * s + be[t];
    }
    __syncthreads();
    int idx = blockIdx.x * 256 + t;
    int co = idx & 63, hw = idx >> 6;
    int hh = hw / 400, ww = hw - hh * 400;
    float s = 0.f;
#pragma unroll
    for (int dh = 0; dh < 3; dh++) {
        int gh = hh + dh - 1;
        if (gh < 0 || gh >= 80) continue;
#pragma unroll
        for (int dw = 0; dw < 3; dw++) {
            int gw = ww + dw - 1;
            if (gw < 0 || gw >= 400) continue;
            s = fmaf(ws[co * 9 + dh * 3 + dw], g_feats[gh * 400 + gw], s);
        }
    }
    g_c1h[idx] = __float2half_rn(fmaxf(fmaf(s, sc[co], sh[co]), 0.f));
}

__global__ void k_bnfold(const float* __restrict__ g, const float* __restrict__ cb,
                         const float* __restrict__ be, float* __restrict__ sc,
                         float* __restrict__ sh, int n) {
    int i = blockIdx.x * 256 + threadIdx.x;
    if (i < n) {
        float s = g[i] * rsqrtf(1.0f + 1e-5f);
        sc[i] = s;
        sh[i] = cb[i] * s + be[i];
    }
}

__global__ void k_wreorder(const float* __restrict__ w, __half* __restrict__ o,
                           int CIN, int total) {
    int idx = blockIdx.x * 256 + threadIdx.x;
    if (idx >= total) return;
    int K = CIN * 9;
    int n = idx / K, r = idx - n * K;
    int ci = r / 9, r9 = r - ci * 9;
    o[n * K + r9 * CIN + ci] = __float2half_rn(w[idx]);
}

// vectorized f32 -> f16 (4 elems/thread)
__global__ void k_tohalf4(const float4* __restrict__ w, uint2* __restrict__ o, int n4) {
    int i = blockIdx.x * 256 + threadIdx.x;
    if (i < n4) {
        float4 v = w[i];
        uint2 u;
        u.x = f2h2(v.x, v.y);
        u.y = f2h2(v.z, v.w);
        o[i] = u;
    }
}

// ---------- fp16-in GEMM, 128x128 tile, BK=32 (conv, implicit im2col) --------
template <int ACT, int LOGC>
__global__ void __launch_bounds__(256) k_mm(
    const __half* __restrict__ A,
    const __half* __restrict__ W,
    const float* __restrict__ bias, const float* __restrict__ scale,
    __half* __restrict__ Ch, int N, int K) {
    extern __shared__ uint32_t sm[];
    uint32_t* Bsm = sm + 4352;
    const int t = threadIdx.x;
    const int lane = t & 31, wid = t >> 5;
    const int wm = (wid & 3) * 32, wn = (wid >> 2) * 64;
    const int g = lane >> 2, c = lane & 3;
    const int lrow = t >> 1, lkq = (t & 1) * 16, kp0 = (t & 1) * 8;
    const int m0 = blockIdx.y * 128, n0 = blockIdx.x * 128;

    int hh = 0, ww = 0;
    {
        int hw = m0 + lrow;
        hh = hw / 400;
        ww = hw - hh * 400;
    }
    const __half* Wp = W + (size_t)(n0 + lrow) * K + lkq;

    float acc[2][8][4];
#pragma unroll
    for (int i = 0; i < 2; i++)
#pragma unroll
        for (int j = 0; j < 8; j++)
#pragma unroll
            for (int q = 0; q < 4; q++) acc[i][j][q] = 0.f;

    uint4 av[2], bv[2];
    auto loadA = [&](int k0c) {
        const int Cm = (1 << LOGC) - 1;
        int k = k0c + lkq;
        int r9 = k >> LOGC, ci = k & Cm;
        int dh = r9 / 3, dw = r9 - dh * 3;
        int gh = hh + dh - 1, gw = ww + dw - 1;
        if (gh >= 0 && gh < 80 && gw >= 0 && gw < 400) {
            const __half* p = A + (((size_t)(gh * 400 + gw)) << LOGC) + ci;
            av[0] = ((const uint4*)p)[0];
            av[1] = ((const uint4*)p)[1];
        } else {
            av[0] = make_uint4(0, 0, 0, 0);
            av[1] = av[0];
        }
    };
    auto loadB = [&]() {
        bv[0] = ((const uint4*)Wp)[0];
        bv[1] = ((const uint4*)Wp)[1];
        Wp += 32;
    };
    auto stsAB = [&](int p) {
        uint32_t* as = sm + p * 2176 + lrow;
        uint32_t* bs = Bsm + p * 2176 + lrow;
#pragma unroll
        for (int j = 0; j < 2; j++) {
            as[(kp0 + j * 4 + 0) * 136] = av[j].x;
            as[(kp0 + j * 4 + 1) * 136] = av[j].y;
            as[(kp0 + j * 4 + 2) * 136] = av[j].z;
            as[(kp0 + j * 4 + 3) * 136] = av[j].w;
            bs[(kp0 + j * 4 + 0) * 136] = bv[j].x;
            bs[(kp0 + j * 4 + 1) * 136] = bv[j].y;
            bs[(kp0 + j * 4 + 2) * 136] = bv[j].z;
            bs[(kp0 + j * 4 + 3) * 136] = bv[j].w;
        }
    };

    loadA(0);
    loadB();
    stsAB(0);
    __syncthreads();
    int p = 0;
    for (int k0 = 0; k0 < K; k0 += 32) {
        bool more = (k0 + 32 < K);
        if (more) { loadA(k0 + 32); loadB(); }
        const uint32_t* as = sm + p * 2176;
        const uint32_t* bs = Bsm + p * 2176;
#pragma unroll
        for (int kk = 0; kk < 16; kk += 8) {
            uint32_t af[2][4];
#pragma unroll
            for (int tm = 0; tm < 2; tm++) {
                int mm = wm + tm * 16;
                af[tm][0] = as[(kk + c) * 136 + mm + g];
                af[tm][1] = as[(kk + c) * 136 + mm + g + 8];
                af[tm][2] = as[(kk + c + 4) * 136 + mm + g];
                af[tm][3] = as[(kk + c + 4) * 136 + mm + g + 8];
            }
#pragma unroll
            for (int tn = 0; tn < 8; tn++) {
                uint32_t bf[2];
                bf[0] = bs[(kk + c) * 136 + wn + tn * 8 + g];
                bf[1] = bs[(kk + c + 4) * 136 + wn + tn * 8 + g];
                mma16(acc[0][tn], af[0], bf);
                mma16(acc[1][tn], af[1], bf);
            }
        }
        if (more) stsAB(p ^ 1);
        __syncthreads();
        p ^= 1;
    }
#pragma unroll
    for (int tm = 0; tm < 2; tm++) {
        int row = m0 + wm + tm * 16 + g;
#pragma unroll
        for (int tn = 0; tn < 8; tn++) {
            int col = n0 + wn + tn * 8 + 2 * c;
            float s0 = scale[col], s1 = scale[col + 1];
            float bb0 = bias[col], bb1 = bias[col + 1];
            float v00 = fmaf(acc[tm][tn][0], s0, bb0);
            float v01 = fmaf(acc[tm][tn][1], s1, bb1);
            float v10 = fmaf(acc[tm][tn][2], s0, bb0);
            float v11 = fmaf(acc[tm][tn][3], s1, bb1);
            if (ACT) {
                v00 = fmaxf(v00, 0.f); v01 = fmaxf(v01, 0.f);
                v10 = fmaxf(v10, 0.f); v11 = fmaxf(v11, 0.f);
            }
            *(uint32_t*)&Ch[(size_t)row * N + col] = f2h2(v00, v01);
            *(uint32_t*)&Ch[(size_t)(row + 8) * N + col] = f2h2(v10, v11);
        }
    }
}

// ---------- fp16-in GEMM, 64xBN tiles, BK=32 (QKV / FF1 / proj) --------------
template <int ACT, int BN, int OUT>
__global__ void __launch_bounds__(256) k_mmS(
    const __half* __restrict__ A, const __half* __restrict__ W,
    const float* __restrict__ bias, float* __restrict__ C,
    __half* __restrict__ Ch, int N, int K) {
    constexpr int BNW = BN / 2, TN = BNW / 8, BP = BN + 8;
    extern __shared__ uint32_t sm[];
    uint32_t* Bsm = sm + 2304;
    const int t = threadIdx.x;
    const int lane = t & 31, wid = t >> 5;
    const int wm = (wid & 3) * 16, wn = (wid >> 2) * BNW;
    const int g = lane >> 2, c = lane & 3;
    const int m0 = blockIdx.y * 64, n0 = blockIdx.x * BN;

    const int rowA = t >> 2, kqA = (t & 3) * 8, kpA = (t & 3) * 4;
    const __half* Ap = A + (size_t)(m0 + rowA) * K + kqA;
    const int rowB = (BN == 128) ? (t >> 1) : (t >> 2);
    const int kqB = (BN == 128) ? ((t & 1) * 16) : ((t & 3) * 8);
    const int kpB = (BN == 128) ? ((t & 1) * 8) : ((t & 3) * 4);
    const __half* Wp = W + (size_t)(n0 + rowB) * K + kqB;

    float acc[TN][4];
#pragma unroll
    for (int j = 0; j < TN; j++)
#pragma unroll
        for (int q = 0; q < 4; q++) acc[j][q] = 0.f;

    uint4 a0, b0, b1;
    auto loadAB = [&]() {
        a0 = *(const uint4*)Ap;
        Ap += 32;
        b0 = ((const uint4*)Wp)[0];
        if (BN == 128) b1 = ((const uint4*)Wp)[1];
        Wp += 32;
    };
    auto stsAB = [&](int p) {
        uint32_t* as = sm + p * 1152 + rowA;
        as[(kpA + 0) * 72] = a0.x;
        as[(kpA + 1) * 72] = a0.y;
        as[(kpA + 2) * 72] = a0.z;
        as[(kpA + 3) * 72] = a0.w;
        uint32_t* bs = Bsm + p * 16 * BP + rowB;
        bs[(kpB + 0) * BP] = b0.x;
        bs[(kpB + 1) * BP] = b0.y;
        bs[(kpB + 2) * BP] = b0.z;
        bs[(kpB + 3) * BP] = b0.w;
        if (BN == 128) {
            bs[(kpB + 4) * BP] = b1.x;
            bs[(kpB + 5) * BP] = b1.y;
            bs[(kpB + 6) * BP] = b1.z;
            bs[(kpB + 7) * BP] = b1.w;
        }
    };

    loadAB();
    stsAB(0);
    __syncthreads();
    int p = 0;
    for (int k0 = 0; k0 < K; k0 += 32) {
        bool more = (k0 + 32 < K);
        if (more) loadAB();
        const uint32_t* as = sm + p * 1152;
        const uint32_t* bs = Bsm + p * 16 * BP;
#pragma unroll
        for (int kk = 0; kk < 16; kk += 8) {
            uint32_t af[4];
            af[0] = as[(kk + c) * 72 + wm + g];
            af[1] = as[(kk + c) * 72 + wm + g + 8];
            af[2] = as[(kk + c + 4) * 72 + wm + g];
            af[3] = as[(kk + c + 4) * 72 + wm + g + 8];
#pragma unroll
            for (int tn = 0; tn < TN; tn++) {
                uint32_t bf[2];
                bf[0] = bs[(kk + c) * BP + wn + tn * 8 + g];
                bf[1] = bs[(kk + c + 4) * BP + wn + tn * 8 + g];
                mma16(acc[tn], af, bf);
            }
        }
        if (more) stsAB(p ^ 1);
        __syncthreads();
        p ^= 1;
    }
    int row = m0 + wm + g;
#pragma unroll
    for (int tn = 0; tn < TN; tn++) {
        int col = n0 + wn + tn * 8 + 2 * c;
        float bb0 = bias[col], bb1 = bias[col + 1];
        float v00 = acc[tn][0] + bb0, v01 = acc[tn][1] + bb1;
        float v10 = acc[tn][2] + bb0, v11 = acc[tn][3] + bb1;
        if (ACT) {
            v00 = fmaxf(v00, 0.f); v01 = fmaxf(v01, 0.f);
            v10 = fmaxf(v10, 0.f); v11 = fmaxf(v11, 0.f);
        }
        if (OUT == 0) {
            *(float2*)&C[(size_t)row * N + col] = make_float2(v00, v01);
            *(float2*)&C[(size_t)(row + 8) * N + col] = make_float2(v10, v11);
        } else {
            *(uint32_t*)&Ch[(size_t)row * N + col] = f2h2(v00, v01);
            *(uint32_t*)&Ch[(size_t)(row + 8) * N + col] = f2h2(v10, v11);
        }
    }
}

// ---- fused GEMM + residual + LayerNorm (N=256): 16-row x 256-col block ------
// x (f32 residual stream) updated in place; xh mirrors in fp16.
__global__ void __launch_bounds__(256) k_mmLN(
    const __half* __restrict__ A, const __half* __restrict__ W,
    const float* __restrict__ bias,
    const float* __restrict__ lg, const float* __restrict__ lb,
    float* __restrict__ x, __half* __restrict__ xh, int K) {
    extern __shared__ uint32_t sm[];           // As[2][16][24] | Bs[2][16][264] | red
    uint32_t* Bsm = sm + 768;
    float* red = (float*)(sm + 9216);          // 8 warps x 16 rows x {sum,sumsq}
    const int t = threadIdx.x;
    const int lane = t & 31, wid = t >> 5;
    const int wn = wid * 32;
    const int g = lane >> 2, c = lane & 3;
    const int m0 = blockIdx.x * 16;

    const int rowA = t >> 3, kpA = (t & 7) * 2;
    const __half* Ap = A + (size_t)(m0 + rowA) * K + kpA * 2;
    const __half* Wp = W + (size_t)t * K;

    float acc[4][4];
#pragma unroll
    for (int j = 0; j < 4; j++)
#pragma unroll
        for (int q = 0; q < 4; q++) acc[j][q] = 0.f;

    uint2 aq;
    uint4 bq[4];
    auto loadAB = [&](int k0) {
        if (t < 128) aq = *(const uint2*)(Ap + k0);
        const uint4* w4 = (const uint4*)(Wp + k0);
        bq[0] = w4[0]; bq[1] = w4[1]; bq[2] = w4[2]; bq[3] = w4[3];
    };
    auto stsAB = [&](int p) {
        if (t < 128) {
            uint32_t* as = sm + p * 384;
            as[(kpA + 0) * 24 + rowA] = aq.x;
            as[(kpA + 1) * 24 + rowA] = aq.y;
        }
        uint32_t* bs = Bsm + p * 4224 + t;
#pragma unroll
        for (int j = 0; j < 4; j++) {
            bs[(j * 4 + 0) * 264] = bq[j].x;
            bs[(j * 4 + 1) * 264] = bq[j].y;
            bs[(j * 4 + 2) * 264] = bq[j].z;
            bs[(j * 4 + 3) * 264] = bq[j].w;
        }
    };

    loadAB(0);
    stsAB(0);
    __syncthreads();
    int p = 0;
    for (int k0 = 0; k0 < K; k0 += 32) {
        bool more = (k0 + 32 < K);
        if (more) loadAB(k0 + 32);
        const uint32_t* as = sm + p * 384;
        const uint32_t* bs = Bsm + p * 4224;
#pragma unroll
        for (int kk = 0; kk < 16; kk += 8) {
            uint32_t af[4];
            af[0] = as[(kk + c) * 24 + g];
            af[1] = as[(kk + c) * 24 + g + 8];
            af[2] = as[(kk + c + 4) * 24 + g];
            af[3] = as[(kk + c + 4) * 24 + g + 8];
#pragma unroll
            for (int tn = 0; tn < 4; tn++) {
                uint32_t bf[2];
                bf[0] = bs[(kk + c) * 264 + wn + tn * 8 + g];
                bf[1] = bs[(kk + c + 4) * 264 + wn + tn * 8 + g];
                mma16(acc[tn], af, bf);
            }
        }
        if (more) stsAB(p ^ 1);
        __syncthreads();
        p ^= 1;
    }

    // epilogue: residual add, LN stats, normalize, write f32 + f16
    int row0 = m0 + g, row1 = m0 + g + 8;
    float v[4][4];
    float s0 = 0.f, q0 = 0.f, s1 = 0.f, q1 = 0.f;
#pragma unroll
    for (int tn = 0; tn < 4; tn++) {
        int col = wn + tn * 8 + 2 * c;
        float bb0 = bias[col], bb1 = bias[col + 1];
        float2 x0 = *(float2*)&x[(size_t)row0 * DM + col];
        float2 x1 = *(float2*)&x[(size_t)row1 * DM + col];
        v[tn][0] = acc[tn][0] + bb0 + x0.x;
        v[tn][1] = acc[tn][1] + bb1 + x0.y;
        v[tn][2] = acc[tn][2] + bb0 + x1.x;
        v[tn][3] = acc[tn][3] + bb1 + x1.y;
        s0 += v[tn][0] + v[tn][1];
        q0 += v[tn][0] * v[tn][0] + v[tn][1] * v[tn][1];
        s1 += v[tn][2] + v[tn][3];
        q1 += v[tn][2] * v[tn][2] + v[tn][3] * v[tn][3];
    }
#pragma unroll
    for (int o = 1; o <= 2; o <<= 1) {
        s0 += __shfl_xor_sync(0xffffffffu, s0, o);
        q0 += __shfl_xor_sync(0xffffffffu, q0, o);
        s1 += __shfl_xor_sync(0xffffffffu, s1, o);
        q1 += __shfl_xor_sync(0xffffffffu, q1, o);
    }
    if (c == 0) {
        red[(wid * 16 + g) * 2 + 0] = s0;
        red[(wid * 16 + g) * 2 + 1] = q0;
        red[(wid * 16 + g + 8) * 2 + 0] = s1;
        red[(wid * 16 + g + 8) * 2 + 1] = q1;
    }
    __syncthreads();
    float S0 = 0.f, Q0 = 0.f, S1 = 0.f, Q1 = 0.f;
#pragma unroll
    for (int w8 = 0; w8 < 8; w8++) {
        S0 += red[(w8 * 16 + g) * 2 + 0];
        Q0 += red[(w8 * 16 + g) * 2 + 1];
        S1 += red[(w8 * 16 + g + 8) * 2 + 0];
        Q1 += red[(w8 * 16 + g + 8) * 2 + 1];
    }
    float mean0 = S0 * (1.0f / DM);
    float inv0 = rsqrtf(Q0 * (1.0f / DM) - mean0 * mean0 + 1e-5f);
    float mean1 = S1 * (1.0f / DM);
    float inv1 = rsqrtf(Q1 * (1.0f / DM) - mean1 * mean1 + 1e-5f);
#pragma unroll
    for (int tn = 0; tn < 4; tn++) {
        int col = wn + tn * 8 + 2 * c;
        float g0 = lg[col], g1 = lg[col + 1];
        float b0 = lb[col], b1 = lb[col + 1];
        float o00 = (v[tn][0] - mean0) * inv0 * g0 + b0;
        float o01 = (v[tn][1] - mean0) * inv0 * g1 + b1;
        float o10 = (v[tn][2] - mean1) * inv1 * g0 + b0;
        float o11 = (v[tn][3] - mean1) * inv1 * g1 + b1;
        *(float2*)&x[(size_t)row0 * DM + col] = make_float2(o00, o01);
        *(float2*)&x[(size_t)row1 * DM + col] = make_float2(o10, o11);
        *(uint32_t*)&xh[(size_t)row0 * DM + col] = f2h2(o00, o01);
        *(uint32_t*)&xh[(size_t)row1 * DM + col] = f2h2(o10, o11);
    }
}

// ------------------------- adaptive pool + tokens ----------------------------
__global__ void k_apool() {
    int idx = blockIdx.x * 256 + threadIdx.x;
    int c = idx & 255, pos = idx >> 8;
    int hh = pos >> 5, wo = pos & 31;
    int st = (wo * 25) >> 1;
    int en = ((wo + 1) * 25 + 1) >> 1;
    float s = 0.f;
    for (int w = st; w < en; w++)
        s += __half2float(g_c3h[(((size_t)(hh * 400 + w)) << 8) + c]);
    float v = s / (float)(en - st);
    g_tok[idx] = v;
    g_tokh[idx] = __float2half_rn(v);
}

// ------------------- flash attention (split-KV, fp16-resident) ---------------
__global__ void __launch_bounds__(256, 2) k_flashp(const __half* __restrict__ qkv,
                                                   float* __restrict__ Opart,
                                                   float* __restrict__ ml) {
    __shared__ uint32_t Ks2[16][72];
    __shared__ uint32_t Vs2[32][40];
    __shared__ uint32_t Ps2[32][136];
    const int h = blockIdx.y;
    const int q0 = blockIdx.x * 128;
    const int z = blockIdx.z;
    const int kbase = z * (SEQ / KSPLIT);
    const int t = threadIdx.x, lane = t & 31, w = t >> 5;
    const int g = lane >> 2, c = lane & 3;
    const int wrow = w * 16;
    const float SC = 0.17677669529663687f;

    uint32_t qf[2][4];
    {
        const __half* Qb = qkv + (size_t)(q0 + wrow) * 768 + h * 32;
#pragma unroll
        for (int kt = 0; kt < 2; kt++) {
            int kb = kt * 16 + 2 * c;
            qf[kt][0] = *(const uint32_t*)(Qb + (size_t)g * 768 + kb);
            qf[kt][1] = *(const uint32_t*)(Qb + (size_t)(g + 8) * 768 + kb);
            qf[kt][2] = *(const uint32_t*)(Qb + (size_t)g * 768 + kb + 8);
            qf[kt][3] = *(const uint32_t*)(Qb + (size_t)(g + 8) * 768 + kb + 8);
        }
    }
    float oacc[4][4];
#pragma unroll
    for (int i = 0; i < 4; i++)
#pragma unroll
        for (int j = 0; j < 4; j++) oacc[i][j] = 0.f;
    float m0 = -1e30f, m1 = -1e30f, l0 = 0.f, l1 = 0.f;

    const int key8 = t >> 3;
    const int dh4 = (t & 7) * 4;
    const int kp2 = (t & 7) * 2;

    uint2 kv0, kv1, vv0, vv1;
    {
        const __half* kvp = qkv + (size_t)(kbase + key8) * 768 + 256 + h * 32 + dh4;
        kv0 = *(const uint2*)kvp;
        vv0 = *(const uint2*)(kvp + 256);
        kvp += (size_t)32 * 768;
        kv1 = *(const uint2*)kvp;
        vv1 = *(const uint2*)(kvp + 256);
    }

    for (int k0 = kbase; k0 < kbase + SEQ / KSPLIT; k0 += KC) {
        __syncthreads();
        {
            Ks2[kp2 + 0][key8] = kv0.x;
            Ks2[kp2 + 1][key8] = kv0.y;
            Ks2[kp2 + 0][key8 + 32] = kv1.x;
            Ks2[kp2 + 1][key8 + 32] = kv1.y;
            const __half* va = (const __half*)&vv0;
            const __half* vb = (const __half*)&vv1;
#pragma unroll
            for (int j = 0; j < 4; j++) {
                ((__half*)&Vs2[key8 >> 1][dh4 + j])[key8 & 1] = va[j];
                ((__half*)&Vs2[(key8 + 32) >> 1][dh4 + j])[key8 & 1] = vb[j];
            }
        }
        __syncthreads();
        if (k0 + KC < kbase + SEQ / KSPLIT) {
            const __half* kvp = qkv + (size_t)(k0 + KC + key8) * 768 + 256 + h * 32 + dh4;
            kv0 = *(const uint2*)kvp;
            vv0 = *(const uint2*)(kvp + 256);
            kvp += (size_t)32 * 768;
            kv1 = *(const uint2*)kvp;
            vv1 = *(const uint2*)(kvp + 256);
        }

        float sacc[8][4];
#pragma unroll
        for (int nt = 0; nt < 8; nt++)
#pragma unroll
            for (int q = 0; q < 4; q++) sacc[nt][q] = 0.f;
#pragma unroll
        for (int kt = 0; kt < 2; kt++) {
#pragma unroll
            for (int nt = 0; nt < 8; nt++) {
                uint32_t bf[2];
                bf[0] = Ks2[kt * 8 + c][nt * 8 + g];
                bf[1] = Ks2[kt * 8 + c + 4][nt * 8 + g];
                mma16(sacc[nt], qf[kt], bf);
            }
        }

        float mx0 = -1e30f, mx1 = -1e30f;
#pragma unroll
        for (int nt = 0; nt < 8; nt++) {
            mx0 = fmaxf(mx0, fmaxf(sacc[nt][0], sacc[nt][1]));
            mx1 = fmaxf(mx1, fmaxf(sacc[nt][2], sacc[nt][3]));
        }
#pragma unroll
        for (int o = 1; o <= 2; o <<= 1) {
            mx0 = fmaxf(mx0, __shfl_xor_sync(0xffffffffu, mx0, o));
            mx1 = fmaxf(mx1, __shfl_xor_sync(0xffffffffu, mx1, o));
        }
        float mn0 = fmaxf(m0, mx0), mn1 = fmaxf(m1, mx1);
        float r0 = __expf((m0 - mn0) * SC), r1 = __expf((m1 - mn1) * SC);
#pragma unroll
        for (int nd = 0; nd < 4; nd++) {
            oacc[nd][0] *= r0; oacc[nd][1] *= r0;
            oacc[nd][2] *= r1; oacc[nd][3] *= r1;
        }
        float s0 = 0.f, s1 = 0.f;
#pragma unroll
        for (int nt = 0; nt < 8; nt++) {
            float p00 = __expf((sacc[nt][0] - mn0) * SC);
            float p01 = __expf((sacc[nt][1] - mn0) * SC);
            float p10 = __expf((sacc[nt][2] - mn1) * SC);
            float p11 = __expf((sacc[nt][3] - mn1) * SC);
            s0 += p00 + p01;
            s1 += p10 + p11;
            Ps2[nt * 4 + c][wrow + g] = f2h2(p00, p01);
            Ps2[nt * 4 + c][wrow + g + 8] = f2h2(p10, p11);
        }
#pragma unroll
        for (int o = 1; o <= 2; o <<= 1) {
            s0 += __shfl_xor_sync(0xffffffffu, s0, o);
            s1 += __shfl_xor_sync(0xffffffffu, s1, o);
        }
        l0 = l0 * r0 + s0;
        l1 = l1 * r1 + s1;
        m0 = mn0; m1 = mn1;
        __syncwarp();

#pragma unroll
        for (int ks = 0; ks < 4; ks++) {
            uint32_t af[4];
            af[0] = Ps2[ks * 8 + c][wrow + g];
            af[1] = Ps2[ks * 8 + c][wrow + g + 8];
            af[2] = Ps2[ks * 8 + c + 4][wrow + g];
            af[3] = Ps2[ks * 8 + c + 4][wrow + g + 8];
#pragma unroll
            for (int nd = 0; nd < 4; nd++) {
                uint32_t bf[2];
                bf[0] = Vs2[ks * 8 + c][nd * 8 + g];
                bf[1] = Vs2[ks * 8 + c + 4][nd * 8 + g];
                mma16(oacc[nd], af, bf);
            }
        }
    }

    float* Oz = Opart + (size_t)z * SEQ * DM;
#pragma unroll
    for (int nd = 0; nd < 4; nd++) {
        int col = h * 32 + nd * 8 + 2 * c;
        int row = q0 + wrow + g;
        *(float2*)&Oz[(size_t)row * DM + col] = make_float2(oacc[nd][0], oacc[nd][1]);
        *(float2*)&Oz[(size_t)(row + 8) * DM + col] = make_float2(oacc[nd][2], oacc[nd][3]);
    }
    if (c == 0) {
        size_t base = (((size_t)z * 8 + h) * SEQ);
        int row = q0 + wrow + g;
        ml[(base + row) * 2 + 0] = m0;
        ml[(base + row) * 2 + 1] = l0;
        ml[(base + row + 8) * 2 + 0] = m1;
        ml[(base + row + 8) * 2 + 1] = l1;
    }
}

__global__ void k_fcomb(const float* __restrict__ Opart, const float* __restrict__ ml,
                        __half* __restrict__ O) {
    int idx = blockIdx.x * 256 + threadIdx.x;
    int row = idx >> 8, col = idx & 255, h = col >> 5;
    const float SC = 0.17677669529663687f;
    float mz[KSPLIT], lz[KSPLIT];
    float M = -1e30f;
#pragma unroll
    for (int z = 0; z < KSPLIT; z++) {
        size_t bi = (((size_t)z * 8 + h) * SEQ + row) * 2;
        mz[z] = ml[bi];
        lz[z] = ml[bi + 1];
        M = fmaxf(M, mz[z]);
    }
    float den = 0.f, num = 0.f;
#pragma unroll
    for (int z = 0; z < KSPLIT; z++) {
        float wz = __expf((mz[z] - M) * SC);
        den += wz * lz[z];
        num += wz * Opart[(size_t)z * SEQ * DM + idx];
    }
    O[idx] = __float2half_rn(num / den);
}

// ------------------------------ launcher -------------------------------------
static void* symAddr(const void* sym) {
    void* p = nullptr;
    cudaGetSymbolAddress(&p, sym);
    return p;
}

#define SMM 34816
#define SMS128 26624
#define SMS64 18432
#define SMLN 37888

extern "C" void kernel_launch(void* const* d_in, const int* in_sizes, int n_in,
                              void* d_out, int out_size) {
    const float* x = (const float*)d_in[0];
    const float* cw1 = (const float*)d_in[1];
    const float* cb1 = (const float*)d_in[2];
    const float* g1 = (const float*)d_in[3];
    const float* be1 = (const float*)d_in[4];
    const float* cw2 = (const float*)d_in[5];
    const float* cb2 = (const float*)d_in[6];
    const float* g2 = (const float*)d_in[7];
    const float* be2 = (const float*)d_in[8];
    const float* cw3 = (const float*)d_in[9];
    const float* cb3 = (const float*)d_in[10];
    const float* g3 = (const float*)d_in[11];
    const float* be3 = (const float*)d_in[12];
    const float* qkv_w = (const float*)d_in[13];
    const float* qkv_b = (const float*)d_in[14];
    const float* out_w = (const float*)d_in[15];
    const float* out_b = (const float*)d_in[16];
    const float* ln1_g = (const float*)d_in[17];
    const float* ln1_b = (const float*)d_in[18];
    const float* ff1_w = (const float*)d_in[19];
    const float* ff1_b = (const float*)d_in[20];
    const float* ff2_w = (const float*)d_in[21];
    const float* ff2_b = (const float*)d_in[22];
    const float* ln2_g = (const float*)d_in[23];
    const float* ln2_b = (const float*)d_in[24];
    const float* pw = (const float*)d_in[25];
    const float* pb = (const float*)d_in[26];

    __half* p_c1h = (__half*)symAddr(g_c1h);
    __half* p_c2h = (__half*)symAddr(g_c2h);
    __half* p_c3h = (__half*)symAddr(g_c3h);
    __half* p_w2rh = (__half*)symAddr(g_w2rh);
    __half* p_w3rh = (__half*)symAddr(g_w3rh);
    float*  p_tok = (float*)symAddr(g_tok);
    __half* p_tokh = (__half*)symAddr(g_tokh);
    __half* p_qkvh = (__half*)symAddr(g_qkvh);
    __half* p_attnOh = (__half*)symAddr(g_attnOh);
    __half* p_ffnh = (__half*)symAddr(g_ffnh);
    float*  p_part = (float*)symAddr(g_part);
    float*  p_ml = (float*)symAddr(g_ml);
    float*  p_sc2 = (float*)symAddr(g_sc2);
    float*  p_sh2 = (float*)symAddr(g_sh2);
    float*  p_sc3 = (float*)symAddr(g_sc3);
    float*  p_sh3 = (float*)symAddr(g_sh3);
    __half* p_wqh = (__half*)symAddr(g_wqh);
    __half* p_woh = (__half*)symAddr(g_woh);
    __half* p_wf1h = (__half*)symAddr(g_wf1h);
    __half* p_wf2h = (__half*)symAddr(g_wf2h);
    __half* p_pwh = (__half*)symAddr(g_pwh);

    // ---- weight fp16 conversion (vectorized) ----
    k_tohalf4<<<1536, 256>>>((const float4*)qkv_w, (uint2*)p_wqh, 8 * 768 * 256 / 4);
    k_tohalf4<<<512, 256>>>((const float4*)out_w, (uint2*)p_woh, 8 * 256 * 256 / 4);
    k_tohalf4<<<2048, 256>>>((const float4*)ff1_w, (uint2*)p_wf1h, 8 * 1024 * 256 / 4);
    k_tohalf4<<<2048, 256>>>((const float4*)ff2_w, (uint2*)p_wf2h, 8 * 256 * 1024 / 4);
    k_tohalf4<<<128, 256>>>((const float4*)pw, (uint2*)p_pwh, 512 * 256 / 4);
    k_wreorder<<<288, 256>>>(cw2, p_w2rh, 64, 128 * 576);
    k_wreorder<<<1152, 256>>>(cw3, p_w3rh, 128, 256 * 1152);

    // ---- cochlear front-end ----
    k_init<<<1, 320>>>();
    k_transpose<<<250, 256>>>(x);
    k_passA<<<125, 256>>>();
    k_scan<<<80, 512>>>(0);
    k_passFix<false><<<125, 256>>>(0, 0);
    k_scan<<<80, 512>>>(1);
    k_passFix<false><<<125, 256>>>(1, 1);
    k_scan<<<80, 512>>>(2);
    k_passFix<false><<<125, 256>>>(2, 0);
    k_scan<<<80, 512>>>(3);
    k_passFix<true><<<125, 256>>>(3, 1);

    // ---- conv stack: fp16-resident implicit-im2col GEMMs ----
    k_conv1<<<8000, 256>>>(cw1, cb1, g1, be1);
    k_bnfold<<<1, 256>>>(g2, cb2, be2, p_sc2, p_sh2, 128);
    k_bnfold<<<1, 256>>>(g3, cb3, be3, p_sc3, p_sh3, 256);
    k_mm<1, 6><<<dim3(1, 250), 256, SMM>>>(p_c1h, p_w2rh, p_sh2, p_sc2, p_c2h, 128, 576);
    k_mm<1, 7><<<dim3(2, 250), 256, SMM>>>(p_c2h, p_w3rh, p_sh3, p_sc3, p_c3h, 256, 1152);
    k_apool<<<2560, 256>>>();

    // ---- transformer encoder (fp16-resident, fused LN) ----
    for (int l = 0; l < 8; l++) {
        k_mmS<0, 128, 1><<<dim3(6, 40), 256, SMS128>>>(
            p_tokh, p_wqh + (size_t)l * 768 * 256, qkv_b + l * 768,
            nullptr, p_qkvh, 768, 256);
        k_flashp<<<dim3(20, 8, KSPLIT), 256>>>(p_qkvh, p_part, p_ml);
        k_fcomb<<<2560, 256>>>(p_part, p_ml, p_attnOh);
        k_mmLN<<<160, 256, SMLN>>>(p_attnOh, p_woh + (size_t)l * 65536,
                                   out_b + l * 256, ln1_g + l * 256, ln1_b + l * 256,
                                   p_tok, p_tokh, 256);
        k_mmS<1, 128, 1><<<dim3(8, 40), 256, SMS128>>>(
            p_tokh, p_wf1h + (size_t)l * 262144, ff1_b + l * 1024,
            nullptr, p_ffnh, 1024, 256);
        k_mmLN<<<160, 256, SMLN>>>(p_ffnh, p_wf2h + (size_t)l * 262144,
                                   ff2_b + l * 256, ln2_g + l * 256, ln2_b + l * 256,
                                   p_tok, p_tokh, 1024);
    }

    // ---- output projection ----
    k_mmS<0, 128, 0><<<dim3(4, 40), 256, SMS128>>>(
        p_tokh, p_pwh, pb, (float*)d_out, nullptr, 512, 256);
}

// round 17
// speedup vs baseline: 1.1934x; 1.1934x over previous
#include <cuda_runtime.h>
#include <cuda_fp16.h>
#include <math.h>
#include <stdint.h>

#define TSAMP 64000
#define LCH 160
#define NCH 400
#define NMEL 80
#define DM 256
#define SEQ 2560
#define DFFN 1024
#define KC 64
#define KSPLIT 4

// ------------ f32 state ------------
__device__ float  g_xT[TSAMP];
__device__ float  g_sigA[NMEL * TSAMP];
__device__ float  g_sigB[NMEL * TSAMP];
__device__ float  g_b0c[4][NMEL], g_b2c[4][NMEL], g_a1c[4][NMEL], g_a2c[4][NMEL];
__device__ double g_a1d[4][NMEL], g_a2d[4][NMEL];
__device__ float  g_Mp[4][NMEL][9][4];
__device__ float  g_f1[NMEL * NCH], g_f2[NMEL * NCH];
__device__ float  g_E1[NMEL * NCH], g_E2[NMEL * NCH];
__device__ float  g_feats[NMEL * NCH];
__device__ float  g_tok[SEQ * DM];
__device__ float  g_part[KSPLIT * SEQ * DM];
__device__ float  g_ml[KSPLIT * 8 * SEQ * 2];
__device__ float  g_tmp[SEQ * DM];
__device__ float  g_sc2[128], g_sh2[128], g_sc3[256], g_sh3[256];

// ------------ fp16-resident activations & weights ------------
__device__ __half g_c1h[32000 * 64];
__device__ __half g_c2h[32000 * 128];
__device__ __half g_c3h[32000 * 256];
__device__ __half g_w2rh[128 * 576];
__device__ __half g_w3rh[256 * 1152];
__device__ __half g_tokh[SEQ * DM];
__device__ __half g_qkvh[SEQ * 3 * DM];
__device__ __half g_attnOh[SEQ * DM];
__device__ __half g_ffnh[SEQ * DFFN];
__device__ __half g_wqh[8 * 768 * 256];
__device__ __half g_woh[8 * 256 * 256];
__device__ __half g_wf1h[8 * 1024 * 256];
__device__ __half g_wf2h[8 * 256 * 1024];
__device__ __half g_pwh[512 * 256];

__device__ __forceinline__ float warpSum(float v) {
#pragma unroll
    for (int o = 16; o > 0; o >>= 1) v += __shfl_xor_sync(0xffffffffu, v, o);
    return v;
}
__device__ __forceinline__ uint32_t f2h2(float x, float y) {
    __half2 h = __floats2half2_rn(x, y);
    return *(uint32_t*)&h;
}
__device__ __forceinline__ void mma16(float* d, const uint32_t* a, const uint32_t* b) {
    asm volatile(
        "mma.sync.aligned.m16n8k16.row.col.f32.f16.f16.f32 "
        "{%0,%1,%2,%3},{%4,%5,%6,%7},{%8,%9},{%0,%1,%2,%3};\n"
        : "+f"(d[0]), "+f"(d[1]), "+f"(d[2]), "+f"(d[3])
        : "r"(a[0]), "r"(a[1]), "r"(a[2]), "r"(a[3]), "r"(b[0]), "r"(b[1]));
}

// ------------------------------ cochlear ------------------------------------
__global__ void k_init() {
    int t = threadIdx.x;
    if (t < NMEL) {
        int m = t;
        double fc = exp(log(80.0) + (log(8000.0) - log(80.0)) * (double)m / 79.0);
        double omega = 2.0 * 3.141592653589793 * fc / 16000.0;
        double sn = sin(omega), cs = cos(omega);
        for (int s = 0; s < 4; s++) {
            double q = 4.0 + 2.0 * (double)s;
            double alpha = sn / (2.0 * q);
            double a0 = 1.0 + alpha;
            g_b0c[s][m] = (float)(alpha / a0);
            g_b2c[s][m] = (float)(-alpha / a0);
            g_a1c[s][m] = (float)(-2.0 * cs / a0);
            g_a2c[s][m] = (float)((1.0 - alpha) / a0);
            g_a1d[s][m] = -2.0 * cs / a0;
            g_a2d[s][m] = (1.0 - alpha) / a0;
        }
    }
    __syncthreads();
    if (t < 4 * NMEL) {
        int s = t / NMEL, m = t - s * NMEL;
        double a1 = g_a1d[s][m], a2 = g_a2d[s][m];
        double p0 = -a1, p1 = -a2, p2 = 1.0, p3 = 0.0;
        for (int it = 1; it < LCH; it++) {
            double n0 = -a1 * p0 - a2 * p2, n1 = -a1 * p1 - a2 * p3;
            p3 = p1; p2 = p0; p0 = n0; p1 = n1;
        }
        double q0 = p0, q1 = p1, q2 = p2, q3 = p3;
        for (int sp = 0; sp < 9; sp++) {
            g_Mp[s][m][sp][0] = (float)q0; g_Mp[s][m][sp][1] = (float)q1;
            g_Mp[s][m][sp][2] = (float)q2; g_Mp[s][m][sp][3] = (float)q3;
            double r0 = q0 * q0 + q1 * q2, r1 = q0 * q1 + q1 * q3;
            double r2 = q2 * q0 + q3 * q2, r3 = q2 * q1 + q3 * q3;
            q0 = r0; q1 = r1; q2 = r2; q3 = r3;
        }
    }
}

__global__ void k_transpose(const float* __restrict__ x) {
    int i = blockIdx.x * 256 + threadIdx.x;
    if (i < TSAMP) g_xT[(i % LCH) * NCH + (i / LCH)] = x[i];
}

__global__ void k_passA() {
    int idx = blockIdx.x * 256 + threadIdx.x;
    if (idx >= NMEL * NCH) return;
    int m = idx / NCH, k = idx - m * NCH;
    float b0 = g_b0c[0][m], b2 = g_b2c[0][m], a1 = g_a1c[0][m], a2 = g_a2c[0][m];
    float xm1 = 0.f, xm2 = 0.f;
    if (k > 0) { xm1 = g_xT[159 * NCH + k - 1]; xm2 = g_xT[158 * NCH + k - 1]; }
    float y1 = 0.f, y2 = 0.f;
    float* Y = g_sigA + (size_t)m * TSAMP;
    for (int t0 = 0; t0 < LCH; t0 += 8) {
        float xv[8];
#pragma unroll
        for (int u = 0; u < 8; u++) xv[u] = g_xT[(t0 + u) * NCH + k];
#pragma unroll
        for (int u = 0; u < 8; u++) {
            float y = b0 * xv[u] + b2 * xm2 - a1 * y1 - a2 * y2;
            xm2 = xm1; xm1 = xv[u]; y2 = y1; y1 = y;
            Y[(t0 + u) * NCH + k] = y;
        }
    }
    g_f1[idx] = y1;
    g_f2[idx] = y2;
}

__global__ void k_scan(int stage) {
    __shared__ float s1[2][NCH], s2[2][NCH];
    int m = blockIdx.x, t = threadIdx.x;
    if (t < NCH) { s1[0][t] = g_f1[m * NCH + t]; s2[0][t] = g_f2[m * NCH + t]; }
    __syncthreads();
    int src = 0;
#pragma unroll
    for (int sp = 0; sp < 9; sp++) {
        int off = 1 << sp;
        float M0 = g_Mp[stage][m][sp][0], M1 = g_Mp[stage][m][sp][1];
        float M2 = g_Mp[stage][m][sp][2], M3 = g_Mp[stage][m][sp][3];
        if (t < NCH) {
            float x1 = s1[src][t], x2 = s2[src][t];
            if (t >= off) {
                float p1 = s1[src][t - off], p2 = s2[src][t - off];
                x1 = fmaf(M0, p1, fmaf(M1, p2, x1));
                x2 = fmaf(M2, p1, fmaf(M3, p2, x2));
            }
            s1[src ^ 1][t] = x1; s2[src ^ 1][t] = x2;
        }
        __syncthreads();
        src ^= 1;
    }
    if (t < NCH) {
        g_E1[m * NCH + t] = t ? s1[src][t - 1] : 0.f;
        g_E2[m * NCH + t] = t ? s2[src][t - 1] : 0.f;
    }
}

template <bool LAST>
__global__ void k_passFix(int stage, int inSel) {
    int idx = blockIdx.x * 256 + threadIdx.x;
    if (idx >= NMEL * NCH) return;
    int m = idx / NCH, k = idx - m * NCH;
    const float* Y = (inSel == 0 ? g_sigA : g_sigB) + (size_t)m * TSAMP;
    float* Yn = (inSel == 0 ? g_sigB : g_sigA) + (size_t)m * TSAMP;
    float a1 = g_a1c[stage][m], a2 = g_a2c[stage][m];
    float e1 = g_E1[idx], e2 = g_E2[idx];
    float h1 = e1, h2 = e2;
    float nb0 = 0.f, nb2 = 0.f, na1 = 0.f, na2 = 0.f;
    if (!LAST) {
        nb0 = g_b0c[stage + 1][m]; nb2 = g_b2c[stage + 1][m];
        na1 = g_a1c[stage + 1][m]; na2 = g_a2c[stage + 1][m];
    }
    float nxm1 = e1, nxm2 = e2, ny1 = 0.f, ny2 = 0.f;
    float acc = 0.f;
    for (int t0 = 0; t0 < LCH; t0 += 8) {
        float yv[8];
#pragma unroll
        for (int u = 0; u < 8; u++) yv[u] = Y[(t0 + u) * NCH + k];
#pragma unroll
        for (int u = 0; u < 8; u++) {
            float h = -a1 * h1 - a2 * h2;
            h2 = h1; h1 = h;
            float y = yv[u] + h;
            if (LAST) {
                acc += fabsf(y);
            } else {
                float ny = nb0 * y + nb2 * nxm2 - na1 * ny1 - na2 * ny2;
                nxm2 = nxm1; nxm1 = y; ny2 = ny1; ny1 = ny;
                Yn[(t0 + u) * NCH + k] = ny;
            }
        }
    }
    if (LAST) {
        g_feats[idx] = logf(acc * (1.0f / 160.0f) + 1e-8f);
    } else {
        g_f1[idx] = ny1;
        g_f2[idx] = ny2;
    }
}

// ------------------------------ conv glue ------------------------------------
__global__ void k_conv1(const float* __restrict__ wt, const float* __restrict__ cb,
                        const float* __restrict__ gg, const float* __restrict__ be) {
    __shared__ float ws[576];
    __shared__ float sc[64], sh[64];
    int t = threadIdx.x;
    for (int i = t; i < 576; i += 256) ws[i] = wt[i];
    if (t < 64) {
        float s = gg[t] * rsqrtf(1.0f + 1e-5f);
        sc[t] = s;
        sh[t] = cb[t] * s + be[t];
    }
    __syncthreads();
    int idx = blockIdx.x * 256 + t;
    int co = idx & 63, hw = idx >> 6;
    int hh = hw / 400, ww = hw - hh * 400;
    float s = 0.f;
#pragma unroll
    for (int dh = 0; dh < 3; dh++) {
        int gh = hh + dh - 1;
        if (gh < 0 || gh >= 80) continue;
#pragma unroll
        for (int dw = 0; dw < 3; dw++) {
            int gw = ww + dw - 1;
            if (gw < 0 || gw >= 400) continue;
            s = fmaf(ws[co * 9 + dh * 3 + dw], g_feats[gh * 400 + gw], s);
        }
    }
    g_c1h[idx] = __float2half_rn(fmaxf(fmaf(s, sc[co], sh[co]), 0.f));
}

__global__ void k_bnfold(const float* __restrict__ g, const float* __restrict__ cb,
                         const float* __restrict__ be, float* __restrict__ sc,
                         float* __restrict__ sh, int n) {
    int i = blockIdx.x * 256 + threadIdx.x;
    if (i < n) {
        float s = g[i] * rsqrtf(1.0f + 1e-5f);
        sc[i] = s;
        sh[i] = cb[i] * s + be[i];
    }
}

__global__ void k_wreorder(const float* __restrict__ w, __half* __restrict__ o,
                           int CIN, int total) {
    int idx = blockIdx.x * 256 + threadIdx.x;
    if (idx >= total) return;
    int K = CIN * 9;
    int n = idx / K, r = idx - n * K;
    int ci = r / 9, r9 = r - ci * 9;
    o[n * K + r9 * CIN + ci] = __float2half_rn(w[idx]);
}

// vectorized f32 -> f16 (4 elems/thread)
__global__ void k_tohalf4(const float4* __restrict__ w, uint2* __restrict__ o, int n4) {
    int i = blockIdx.x * 256 + threadIdx.x;
    if (i < n4) {
        float4 v = w[i];
        uint2 u;
        u.x = f2h2(v.x, v.y);
        u.y = f2h2(v.z, v.w);
        o[i] = u;
    }
}

// ---------- fp16-in GEMM, 128x128 tile, BK=32 (conv, implicit im2col) --------
template <int ACT, int LOGC>
__global__ void __launch_bounds__(256) k_mm(
    const __half* __restrict__ A,
    const __half* __restrict__ W,
    const float* __restrict__ bias, const float* __restrict__ scale,
    __half* __restrict__ Ch, int N, int K) {
    extern __shared__ uint32_t sm[];
    uint32_t* Bsm = sm + 4352;
    const int t = threadIdx.x;
    const int lane = t & 31, wid = t >> 5;
    const int wm = (wid & 3) * 32, wn = (wid >> 2) * 64;
    const int g = lane >> 2, c = lane & 3;
    const int lrow = t >> 1, lkq = (t & 1) * 16, kp0 = (t & 1) * 8;
    const int m0 = blockIdx.y * 128, n0 = blockIdx.x * 128;

    int hh = 0, ww = 0;
    {
        int hw = m0 + lrow;
        hh = hw / 400;
        ww = hw - hh * 400;
    }
    const __half* Wp = W + (size_t)(n0 + lrow) * K + lkq;

    float acc[2][8][4];
#pragma unroll
    for (int i = 0; i < 2; i++)
#pragma unroll
        for (int j = 0; j < 8; j++)
#pragma unroll
            for (int q = 0; q < 4; q++) acc[i][j][q] = 0.f;

    uint4 av[2], bv[2];
    auto loadA = [&](int k0c) {
        const int Cm = (1 << LOGC) - 1;
        int k = k0c + lkq;
        int r9 = k >> LOGC, ci = k & Cm;
        int dh = r9 / 3, dw = r9 - dh * 3;
        int gh = hh + dh - 1, gw = ww + dw - 1;
        if (gh >= 0 && gh < 80 && gw >= 0 && gw < 400) {
            const __half* p = A + (((size_t)(gh * 400 + gw)) << LOGC) + ci;
            av[0] = ((const uint4*)p)[0];
            av[1] = ((const uint4*)p)[1];
        } else {
            av[0] = make_uint4(0, 0, 0, 0);
            av[1] = av[0];
        }
    };
    auto loadB = [&]() {
        bv[0] = ((const uint4*)Wp)[0];
        bv[1] = ((const uint4*)Wp)[1];
        Wp += 32;
    };
    auto stsAB = [&](int p) {
        uint32_t* as = sm + p * 2176 + lrow;
        uint32_t* bs = Bsm + p * 2176 + lrow;
#pragma unroll
        for (int j = 0; j < 2; j++) {
            as[(kp0 + j * 4 + 0) * 136] = av[j].x;
            as[(kp0 + j * 4 + 1) * 136] = av[j].y;
            as[(kp0 + j * 4 + 2) * 136] = av[j].z;
            as[(kp0 + j * 4 + 3) * 136] = av[j].w;
            bs[(kp0 + j * 4 + 0) * 136] = bv[j].x;
            bs[(kp0 + j * 4 + 1) * 136] = bv[j].y;
            bs[(kp0 + j * 4 + 2) * 136] = bv[j].z;
            bs[(kp0 + j * 4 + 3) * 136] = bv[j].w;
        }
    };

    loadA(0);
    loadB();
    stsAB(0);
    __syncthreads();
    int p = 0;
    for (int k0 = 0; k0 < K; k0 += 32) {
        bool more = (k0 + 32 < K);
        if (more) { loadA(k0 + 32); loadB(); }
        const uint32_t* as = sm + p * 2176;
        const uint32_t* bs = Bsm + p * 2176;
#pragma unroll
        for (int kk = 0; kk < 16; kk += 8) {
            uint32_t af[2][4];
#pragma unroll
            for (int tm = 0; tm < 2; tm++) {
                int mm = wm + tm * 16;
                af[tm][0] = as[(kk + c) * 136 + mm + g];
                af[tm][1] = as[(kk + c) * 136 + mm + g + 8];
                af[tm][2] = as[(kk + c + 4) * 136 + mm + g];
                af[tm][3] = as[(kk + c + 4) * 136 + mm + g + 8];
            }
#pragma unroll
            for (int tn = 0; tn < 8; tn++) {
                uint32_t bf[2];
                bf[0] = bs[(kk + c) * 136 + wn + tn * 8 + g];
                bf[1] = bs[(kk + c + 4) * 136 + wn + tn * 8 + g];
                mma16(acc[0][tn], af[0], bf);
                mma16(acc[1][tn], af[1], bf);
            }
        }
        if (more) stsAB(p ^ 1);
        __syncthreads();
        p ^= 1;
    }
#pragma unroll
    for (int tm = 0; tm < 2; tm++) {
        int row = m0 + wm + tm * 16 + g;
#pragma unroll
        for (int tn = 0; tn < 8; tn++) {
            int col = n0 + wn + tn * 8 + 2 * c;
            float s0 = scale[col], s1 = scale[col + 1];
            float bb0 = bias[col], bb1 = bias[col + 1];
            float v00 = fmaf(acc[tm][tn][0], s0, bb0);
            float v01 = fmaf(acc[tm][tn][1], s1, bb1);
            float v10 = fmaf(acc[tm][tn][2], s0, bb0);
            float v11 = fmaf(acc[tm][tn][3], s1, bb1);
            if (ACT) {
                v00 = fmaxf(v00, 0.f); v01 = fmaxf(v01, 0.f);
                v10 = fmaxf(v10, 0.f); v11 = fmaxf(v11, 0.f);
            }
            *(uint32_t*)&Ch[(size_t)row * N + col] = f2h2(v00, v01);
            *(uint32_t*)&Ch[(size_t)(row + 8) * N + col] = f2h2(v10, v11);
        }
    }
}

// ---------- fp16-in GEMM, 64xBN tiles, BK=32 (transformer) -------------------
template <int ACT, int BN, int OUT>
__global__ void __launch_bounds__(256) k_mmS(
    const __half* __restrict__ A, const __half* __restrict__ W,
    const float* __restrict__ bias, float* __restrict__ C,
    __half* __restrict__ Ch, int N, int K) {
    constexpr int BNW = BN / 2, TN = BNW / 8, BP = BN + 8;
    extern __shared__ uint32_t sm[];
    uint32_t* Bsm = sm + 2304;
    const int t = threadIdx.x;
    const int lane = t & 31, wid = t >> 5;
    const int wm = (wid & 3) * 16, wn = (wid >> 2) * BNW;
    const int g = lane >> 2, c = lane & 3;
    const int m0 = blockIdx.y * 64, n0 = blockIdx.x * BN;

    const int rowA = t >> 2, kqA = (t & 3) * 8, kpA = (t & 3) * 4;
    const __half* Ap = A + (size_t)(m0 + rowA) * K + kqA;
    const int rowB = (BN == 128) ? (t >> 1) : (t >> 2);
    const int kqB = (BN == 128) ? ((t & 1) * 16) : ((t & 3) * 8);
    const int kpB = (BN == 128) ? ((t & 1) * 8) : ((t & 3) * 4);
    const __half* Wp = W + (size_t)(n0 + rowB) * K + kqB;

    float acc[TN][4];
#pragma unroll
    for (int j = 0; j < TN; j++)
#pragma unroll
        for (int q = 0; q < 4; q++) acc[j][q] = 0.f;

    uint4 a0, b0, b1;
    auto loadAB = [&]() {
        a0 = *(const uint4*)Ap;
        Ap += 32;
        b0 = ((const uint4*)Wp)[0];
        if (BN == 128) b1 = ((const uint4*)Wp)[1];
        Wp += 32;
    };
    auto stsAB = [&](int p) {
        uint32_t* as = sm + p * 1152 + rowA;
        as[(kpA + 0) * 72] = a0.x;
        as[(kpA + 1) * 72] = a0.y;
        as[(kpA + 2) * 72] = a0.z;
        as[(kpA + 3) * 72] = a0.w;
        uint32_t* bs = Bsm + p * 16 * BP + rowB;
        bs[(kpB + 0) * BP] = b0.x;
        bs[(kpB + 1) * BP] = b0.y;
        bs[(kpB + 2) * BP] = b0.z;
        bs[(kpB + 3) * BP] = b0.w;
        if (BN == 128) {
            bs[(kpB + 4) * BP] = b1.x;
            bs[(kpB + 5) * BP] = b1.y;
            bs[(kpB + 6) * BP] = b1.z;
            bs[(kpB + 7) * BP] = b1.w;
        }
    };

    loadAB();
    stsAB(0);
    __syncthreads();
    int p = 0;
    for (int k0 = 0; k0 < K; k0 += 32) {
        bool more = (k0 + 32 < K);
        if (more) loadAB();
        const uint32_t* as = sm + p * 1152;
        const uint32_t* bs = Bsm + p * 16 * BP;
#pragma unroll
        for (int kk = 0; kk < 16; kk += 8) {
            uint32_t af[4];
            af[0] = as[(kk + c) * 72 + wm + g];
            af[1] = as[(kk + c) * 72 + wm + g + 8];
            af[2] = as[(kk + c + 4) * 72 + wm + g];
            af[3] = as[(kk + c + 4) * 72 + wm + g + 8];
#pragma unroll
            for (int tn = 0; tn < TN; tn++) {
                uint32_t bf[2];
                bf[0] = bs[(kk + c) * BP + wn + tn * 8 + g];
                bf[1] = bs[(kk + c + 4) * BP + wn + tn * 8 + g];
                mma16(acc[tn], af, bf);
            }
        }
        if (more) stsAB(p ^ 1);
        __syncthreads();
        p ^= 1;
    }
    int row = m0 + wm + g;
#pragma unroll
    for (int tn = 0; tn < TN; tn++) {
        int col = n0 + wn + tn * 8 + 2 * c;
        float bb0 = bias[col], bb1 = bias[col + 1];
        float v00 = acc[tn][0] + bb0, v01 = acc[tn][1] + bb1;
        float v10 = acc[tn][2] + bb0, v11 = acc[tn][3] + bb1;
        if (ACT) {
            v00 = fmaxf(v00, 0.f); v01 = fmaxf(v01, 0.f);
            v10 = fmaxf(v10, 0.f); v11 = fmaxf(v11, 0.f);
        }
        if (OUT == 0) {
            *(float2*)&C[(size_t)row * N + col] = make_float2(v00, v01);
            *(float2*)&C[(size_t)(row + 8) * N + col] = make_float2(v10, v11);
        } else {
            *(uint32_t*)&Ch[(size_t)row * N + col] = f2h2(v00, v01);
            *(uint32_t*)&Ch[(size_t)(row + 8) * N + col] = f2h2(v10, v11);
        }
    }
}

// ------------------------- adaptive pool + tokens ----------------------------
__global__ void k_apool() {
    int idx = blockIdx.x * 256 + threadIdx.x;
    int c = idx & 255, pos = idx >> 8;
    int hh = pos >> 5, wo = pos & 31;
    int st = (wo * 25) >> 1;
    int en = ((wo + 1) * 25 + 1) >> 1;
    float s = 0.f;
    for (int w = st; w < en; w++)
        s += __half2float(g_c3h[(((size_t)(hh * 400 + w)) << 8) + c]);
    float v = s / (float)(en - st);
    g_tok[idx] = v;
    g_tokh[idx] = __float2half_rn(v);
}

// ------------------- flash attention (split-KV, fp16-resident) ---------------
__global__ void __launch_bounds__(256, 2) k_flashp(const __half* __restrict__ qkv,
                                                   float* __restrict__ Opart,
                                                   float* __restrict__ ml) {
    __shared__ uint32_t Ks2[16][72];
    __shared__ uint32_t Vs2[32][40];
    __shared__ uint32_t Ps2[32][136];
    const int h = blockIdx.y;
    const int q0 = blockIdx.x * 128;
    const int z = blockIdx.z;
    const int kbase = z * (SEQ / KSPLIT);
    const int t = threadIdx.x, lane = t & 31, w = t >> 5;
    const int g = lane >> 2, c = lane & 3;
    const int wrow = w * 16;
    const float SC = 0.17677669529663687f;

    uint32_t qf[2][4];
    {
        const __half* Qb = qkv + (size_t)(q0 + wrow) * 768 + h * 32;
#pragma unroll
        for (int kt = 0; kt < 2; kt++) {
            int kb = kt * 16 + 2 * c;
            qf[kt][0] = *(const uint32_t*)(Qb + (size_t)g * 768 + kb);
            qf[kt][1] = *(const uint32_t*)(Qb + (size_t)(g + 8) * 768 + kb);
            qf[kt][2] = *(const uint32_t*)(Qb + (size_t)g * 768 + kb + 8);
            qf[kt][3] = *(const uint32_t*)(Qb + (size_t)(g + 8) * 768 + kb + 8);
        }
    }
    float oacc[4][4];
#pragma unroll
    for (int i = 0; i < 4; i++)
#pragma unroll
        for (int j = 0; j < 4; j++) oacc[i][j] = 0.f;
    float m0 = -1e30f, m1 = -1e30f, l0 = 0.f, l1 = 0.f;

    const int key8 = t >> 3;
    const int dh4 = (t & 7) * 4;
    const int kp2 = (t & 7) * 2;

    uint2 kv0, kv1, vv0, vv1;
    {
        const __half* kvp = qkv + (size_t)(kbase + key8) * 768 + 256 + h * 32 + dh4;
        kv0 = *(const uint2*)kvp;
        vv0 = *(const uint2*)(kvp + 256);
        kvp += (size_t)32 * 768;
        kv1 = *(const uint2*)kvp;
        vv1 = *(const uint2*)(kvp + 256);
    }

    for (int k0 = kbase; k0 < kbase + SEQ / KSPLIT; k0 += KC) {
        __syncthreads();
        {
            Ks2[kp2 + 0][key8] = kv0.x;
            Ks2[kp2 + 1][key8] = kv0.y;
            Ks2[kp2 + 0][key8 + 32] = kv1.x;
            Ks2[kp2 + 1][key8 + 32] = kv1.y;
            const __half* va = (const __half*)&vv0;
            const __half* vb = (const __half*)&vv1;
#pragma unroll
            for (int j = 0; j < 4; j++) {
                ((__half*)&Vs2[key8 >> 1][dh4 + j])[key8 & 1] = va[j];
                ((__half*)&Vs2[(key8 + 32) >> 1][dh4 + j])[key8 & 1] = vb[j];
            }
        }
        __syncthreads();
        if (k0 + KC < kbase + SEQ / KSPLIT) {
            const __half* kvp = qkv + (size_t)(k0 + KC + key8) * 768 + 256 + h * 32 + dh4;
            kv0 = *(const uint2*)kvp;
            vv0 = *(const uint2*)(kvp + 256);
            kvp += (size_t)32 * 768;
            kv1 = *(const uint2*)kvp;
            vv1 = *(const uint2*)(kvp + 256);
        }

        float sacc[8][4];
#pragma unroll
        for (int nt = 0; nt < 8; nt++)
#pragma unroll
            for (int q = 0; q < 4; q++) sacc[nt][q] = 0.f;
#pragma unroll
        for (int kt = 0; kt < 2; kt++) {
#pragma unroll
            for (int nt = 0; nt < 8; nt++) {
                uint32_t bf[2];
                bf[0] = Ks2[kt * 8 + c][nt * 8 + g];
                bf[1] = Ks2[kt * 8 + c + 4][nt * 8 + g];
                mma16(sacc[nt], qf[kt], bf);
            }
        }

        float mx0 = -1e30f, mx1 = -1e30f;
#pragma unroll
        for (int nt = 0; nt < 8; nt++) {
            mx0 = fmaxf(mx0, fmaxf(sacc[nt][0], sacc[nt][1]));
            mx1 = fmaxf(mx1, fmaxf(sacc[nt][2], sacc[nt][3]));
        }
#pragma unroll
        for (int o = 1; o <= 2; o <<= 1) {
            mx0 = fmaxf(mx0, __shfl_xor_sync(0xffffffffu, mx0, o));
            mx1 = fmaxf(mx1, __shfl_xor_sync(0xffffffffu, mx1, o));
        }
        float mn0 = fmaxf(m0, mx0), mn1 = fmaxf(m1, mx1);
        float r0 = __expf((m0 - mn0) * SC), r1 = __expf((m1 - mn1) * SC);
#pragma unroll
        for (int nd = 0; nd < 4; nd++) {
            oacc[nd][0] *= r0; oacc[nd][1] *= r0;
            oacc[nd][2] *= r1; oacc[nd][3] *= r1;
        }
        float s0 = 0.f, s1 = 0.f;
#pragma unroll
        for (int nt = 0; nt < 8; nt++) {
            float p00 = __expf((sacc[nt][0] - mn0) * SC);
            float p01 = __expf((sacc[nt][1] - mn0) * SC);
            float p10 = __expf((sacc[nt][2] - mn1) * SC);
            float p11 = __expf((sacc[nt][3] - mn1) * SC);
            s0 += p00 + p01;
            s1 += p10 + p11;
            Ps2[nt * 4 + c][wrow + g] = f2h2(p00, p01);
            Ps2[nt * 4 + c][wrow + g + 8] = f2h2(p10, p11);
        }
#pragma unroll
        for (int o = 1; o <= 2; o <<= 1) {
            s0 += __shfl_xor_sync(0xffffffffu, s0, o);
            s1 += __shfl_xor_sync(0xffffffffu, s1, o);
        }
        l0 = l0 * r0 + s0;
        l1 = l1 * r1 + s1;
        m0 = mn0; m1 = mn1;
        __syncwarp();

#pragma unroll
        for (int ks = 0; ks < 4; ks++) {
            uint32_t af[4];
            af[0] = Ps2[ks * 8 + c][wrow + g];
            af[1] = Ps2[ks * 8 + c][wrow + g + 8];
            af[2] = Ps2[ks * 8 + c + 4][wrow + g];
            af[3] = Ps2[ks * 8 + c + 4][wrow + g + 8];
#pragma unroll
            for (int nd = 0; nd < 4; nd++) {
                uint32_t bf[2];
                bf[0] = Vs2[ks * 8 + c][nd * 8 + g];
                bf[1] = Vs2[ks * 8 + c + 4][nd * 8 + g];
                mma16(oacc[nd], af, bf);
            }
        }
    }

    float* Oz = Opart + (size_t)z * SEQ * DM;
#pragma unroll
    for (int nd = 0; nd < 4; nd++) {
        int col = h * 32 + nd * 8 + 2 * c;
        int row = q0 + wrow + g;
        *(float2*)&Oz[(size_t)row * DM + col] = make_float2(oacc[nd][0], oacc[nd][1]);
        *(float2*)&Oz[(size_t)(row + 8) * DM + col] = make_float2(oacc[nd][2], oacc[nd][3]);
    }
    if (c == 0) {
        size_t base = (((size_t)z * 8 + h) * SEQ);
        int row = q0 + wrow + g;
        ml[(base + row) * 2 + 0] = m0;
        ml[(base + row) * 2 + 1] = l0;
        ml[(base + row + 8) * 2 + 0] = m1;
        ml[(base + row + 8) * 2 + 1] = l1;
    }
}

__global__ void k_fcomb(const float* __restrict__ Opart, const float* __restrict__ ml,
                        __half* __restrict__ O) {
    int idx = blockIdx.x * 256 + threadIdx.x;
    int row = idx >> 8, col = idx & 255, h = col >> 5;
    const float SC = 0.17677669529663687f;
    float mz[KSPLIT], lz[KSPLIT];
    float M = -1e30f;
#pragma unroll
    for (int z = 0; z < KSPLIT; z++) {
        size_t bi = (((size_t)z * 8 + h) * SEQ + row) * 2;
        mz[z] = ml[bi];
        lz[z] = ml[bi + 1];
        M = fmaxf(M, mz[z]);
    }
    float den = 0.f, num = 0.f;
#pragma unroll
    for (int z = 0; z < KSPLIT; z++) {
        float wz = __expf((mz[z] - M) * SC);
        den += wz * lz[z];
        num += wz * Opart[(size_t)z * SEQ * DM + idx];
    }
    O[idx] = __float2half_rn(num / den);
}

// -------------------------- residual + LayerNorm -----------------------------
__global__ void k_addln(float* __restrict__ x, __half* __restrict__ xh,
                        const float* __restrict__ r,
                        const float* __restrict__ g, const float* __restrict__ b) {
    int row = blockIdx.x * 8 + (threadIdx.x >> 5);
    int lane = threadIdx.x & 31;
    float v[8];
    float s = 0.f;
#pragma unroll
    for (int i = 0; i < 8; i++) {
        int idx = row * DM + lane + i * 32;
        v[i] = x[idx] + r[idx];
        s += v[i];
    }
    s = warpSum(s);
    float mean = s * (1.0f / DM);
    float var = 0.f;
#pragma unroll
    for (int i = 0; i < 8; i++) {
        float d = v[i] - mean;
        var += d * d;
    }
    var = warpSum(var) * (1.0f / DM);
    float inv = rsqrtf(var + 1e-5f);
#pragma unroll
    for (int i = 0; i < 8; i++) {
        int c = lane + i * 32;
        float o = (v[i] - mean) * inv * g[c] + b[c];
        x[row * DM + c] = o;
        xh[row * DM + c] = __float2half_rn(o);
    }
}

// ------------------------------ launcher -------------------------------------
static void* symAddr(const void* sym) {
    void* p = nullptr;
    cudaGetSymbolAddress(&p, sym);
    return p;
}

#define SMM 34816
#define SMS128 26624
#define SMS64 18432

extern "C" void kernel_launch(void* const* d_in, const int* in_sizes, int n_in,
                              void* d_out, int out_size) {
    const float* x = (const float*)d_in[0];
    const float* cw1 = (const float*)d_in[1];
    const float* cb1 = (const float*)d_in[2];
    const float* g1 = (const float*)d_in[3];
    const float* be1 = (const float*)d_in[4];
    const float* cw2 = (const float*)d_in[5];
    const float* cb2 = (const float*)d_in[6];
    const float* g2 = (const float*)d_in[7];
    const float* be2 = (const float*)d_in[8];
    const float* cw3 = (const float*)d_in[9];
    const float* cb3 = (const float*)d_in[10];
    const float* g3 = (const float*)d_in[11];
    const float* be3 = (const float*)d_in[12];
    const float* qkv_w = (const float*)d_in[13];
    const float* qkv_b = (const float*)d_in[14];
    const float* out_w = (const float*)d_in[15];
    const float* out_b = (const float*)d_in[16];
    const float* ln1_g = (const float*)d_in[17];
    const float* ln1_b = (const float*)d_in[18];
    const float* ff1_w = (const float*)d_in[19];
    const float* ff1_b = (const float*)d_in[20];
    const float* ff2_w = (const float*)d_in[21];
    const float* ff2_b = (const float*)d_in[22];
    const float* ln2_g = (const float*)d_in[23];
    const float* ln2_b = (const float*)d_in[24];
    const float* pw = (const float*)d_in[25];
    const float* pb = (const float*)d_in[26];

    __half* p_c1h = (__half*)symAddr(g_c1h);
    __half* p_c2h = (__half*)symAddr(g_c2h);
    __half* p_c3h = (__half*)symAddr(g_c3h);
    __half* p_w2rh = (__half*)symAddr(g_w2rh);
    __half* p_w3rh = (__half*)symAddr(g_w3rh);
    float*  p_tok = (float*)symAddr(g_tok);
    __half* p_tokh = (__half*)symAddr(g_tokh);
    __half* p_qkvh = (__half*)symAddr(g_qkvh);
    __half* p_attnOh = (__half*)symAddr(g_attnOh);
    __half* p_ffnh = (__half*)symAddr(g_ffnh);
    float*  p_part = (float*)symAddr(g_part);
    float*  p_ml = (float*)symAddr(g_ml);
    float*  p_tmp = (float*)symAddr(g_tmp);
    float*  p_sc2 = (float*)symAddr(g_sc2);
    float*  p_sh2 = (float*)symAddr(g_sh2);
    float*  p_sc3 = (float*)symAddr(g_sc3);
    float*  p_sh3 = (float*)symAddr(g_sh3);
    __half* p_wqh = (__half*)symAddr(g_wqh);
    __half* p_woh = (__half*)symAddr(g_woh);
    __half* p_wf1h = (__half*)symAddr(g_wf1h);
    __half* p_wf2h = (__half*)symAddr(g_wf2h);
    __half* p_pwh = (__half*)symAddr(g_pwh);

    // ---- weight fp16 conversion (vectorized) ----
    k_tohalf4<<<1536, 256>>>((const float4*)qkv_w, (uint2*)p_wqh, 8 * 768 * 256 / 4);
    k_tohalf4<<<512, 256>>>((const float4*)out_w, (uint2*)p_woh, 8 * 256 * 256 / 4);
    k_tohalf4<<<2048, 256>>>((const float4*)ff1_w, (uint2*)p_wf1h, 8 * 1024 * 256 / 4);
    k_tohalf4<<<2048, 256>>>((const float4*)ff2_w, (uint2*)p_wf2h, 8 * 256 * 1024 / 4);
    k_tohalf4<<<128, 256>>>((const float4*)pw, (uint2*)p_pwh, 512 * 256 / 4);
    k_wreorder<<<288, 256>>>(cw2, p_w2rh, 64, 128 * 576);
    k_wreorder<<<1152, 256>>>(cw3, p_w3rh, 128, 256 * 1152);

    // ---- cochlear front-end ----
    k_init<<<1, 320>>>();
    k_transpose<<<250, 256>>>(x);
    k_passA<<<125, 256>>>();
    k_scan<<<80, 512>>>(0);
    k_passFix<false><<<125, 256>>>(0, 0);
    k_scan<<<80, 512>>>(1);
    k_passFix<false><<<125, 256>>>(1, 1);
    k_scan<<<80, 512>>>(2);
    k_passFix<false><<<125, 256>>>(2, 0);
    k_scan<<<80, 512>>>(3);
    k_passFix<true><<<125, 256>>>(3, 1);

    // ---- conv stack: fp16-resident implicit-im2col GEMMs ----
    k_conv1<<<8000, 256>>>(cw1, cb1, g1, be1);
    k_bnfold<<<1, 256>>>(g2, cb2, be2, p_sc2, p_sh2, 128);
    k_bnfold<<<1, 256>>>(g3, cb3, be3, p_sc3, p_sh3, 256);
    k_mm<1, 6><<<dim3(1, 250), 256, SMM>>>(p_c1h, p_w2rh, p_sh2, p_sc2, p_c2h, 128, 576);
    k_mm<1, 7><<<dim3(2, 250), 256, SMM>>>(p_c2h, p_w3rh, p_sh3, p_sc3, p_c3h, 256, 1152);
    k_apool<<<2560, 256>>>();

    // ---- transformer encoder (fp16-resident) ----
    for (int l = 0; l < 8; l++) {
        k_mmS<0, 128, 1><<<dim3(6, 40), 256, SMS128>>>(
            p_tokh, p_wqh + (size_t)l * 768 * 256, qkv_b + l * 768,
            nullptr, p_qkvh, 768, 256);
        k_flashp<<<dim3(20, 8, KSPLIT), 256>>>(p_qkvh, p_part, p_ml);
        k_fcomb<<<2560, 256>>>(p_part, p_ml, p_attnOh);
        k_mmS<0, 64, 0><<<dim3(4, 40), 256, SMS64>>>(
            p_attnOh, p_woh + (size_t)l * 65536, out_b + l * 256,
            p_tmp, nullptr, 256, 256);
        k_addln<<<320, 256>>>(p_tok, p_tokh, p_tmp, ln1_g + l * 256, ln1_b + l * 256);
        k_mmS<1, 128, 1><<<dim3(8, 40), 256, SMS128>>>(
            p_tokh, p_wf1h + (size_t)l * 262144, ff1_b + l * 1024,
            nullptr, p_ffnh, 1024, 256);
        k_mmS<0, 64, 0><<<dim3(4, 40), 256, SMS64>>>(
            p_ffnh, p_wf2h + (size_t)l * 262144, ff2_b + l * 256,
            p_tmp, nullptr, 256, 1024);
        k_addln<<<320, 256>>>(p_tok, p_tokh, p_tmp, ln2_g + l * 256, ln2_b + l * 256);
    }

    // ---- output projection ----
    k_mmS<0, 128, 0><<<dim3(4, 40), 256, SMS128>>>(
        p_tokh, p_pwh, pb, (float*)d_out, nullptr, 512, 256);
}